// round 10
// baseline (speedup 1.0000x reference)
#include <cuda_runtime.h>
#include <math.h>

#define NPTS 65536
#define NWP  128
#define TPB  256
#define PPB  32            // points per block; 8 chunks of 16 waypoints, chunk = warp
#define CLEN 16

#define C_L2E       1.4426950408889634f
#define C_THIRD     0.3333333333333333f

__device__ __forceinline__ float rsqrt_a(float x){ float r; asm("rsqrt.approx.f32 %0,%1;":"=f"(r):"f"(x)); return r; }
__device__ __forceinline__ float rcp_a  (float x){ float r; asm("rcp.approx.f32 %0,%1;"  :"=f"(r):"f"(x)); return r; }
__device__ __forceinline__ float ex2_a  (float x){ float r; asm("ex2.approx.f32 %0,%1;"  :"=f"(r):"f"(x)); return r; }

__global__ void __launch_bounds__(TPB)
fused_kernel(const float* __restrict__ points,      // [N,3]  (z column is exactly 0)
             const float* __restrict__ centers,     // [128,3]
             const float* __restrict__ raw_moment,  // [128,3]
             const float* __restrict__ raw_dwell,   // [128]
             float* __restrict__ out)                // [N,5]
{
    // Per waypoint j (decay weight w = exp(-0.1*(127-j)) folded into the moment):
    //   sA = (cx, cy, cz^2, w*m3x) ; sB = (w*m3y, -cz*w*m3z)   [m3 = 3*moment]
    __shared__ float4 sA[NWP];
    __shared__ float2 sB[NWP];
    __shared__ float2 sW127;         // (cz, m3z) for the wp-127 orientation (w=1 there)
    __shared__ float  sPk[7][PPB];
    __shared__ float  sAt[4];
    __shared__ float  sOut[PPB * 5];

    const int tid = threadIdx.x;

    // ---- preload: transform waypoints (fast ex2/rcp forms), reduce sum(dwell) ----
    if (tid < NWP) {
        const int w = tid;
        float cx = centers[w * 3 + 0];
        float cy = centers[w * 3 + 1];
        float cz = centers[w * 3 + 2];
        // tanh(x) = 1 - 2/(e^{2x}+1)
        float tx = 1.0f - 2.0f * rcp_a(ex2_a(2.0f * C_L2E * raw_moment[w * 3 + 0]) + 1.0f);
        float ty = 1.0f - 2.0f * rcp_a(ex2_a(2.0f * C_L2E * raw_moment[w * 3 + 1]) + 1.0f);
        float tz = 1.0f - 2.0f * rcp_a(ex2_a(2.0f * C_L2E * raw_moment[w * 3 + 2]) + 1.0f);
        float wgt = ex2_a((float)(w - 127) * (0.1f * C_L2E));   // exp(-0.1*(127-j))
        float sm  = 0.15f * wgt;                                 // 3 * 0.05 * weight
        float m3x = sm * tx, m3y = sm * ty, m3z = sm * tz;
        sA[w] = make_float4(cx, cy, cz * cz, m3x);
        sB[w] = make_float2(m3y, -cz * m3z);
        if (w == NWP - 1) sW127 = make_float2(cz, 0.15f * tz);
        // sigmoid via ex2
        float sig = rcp_a(1.0f + ex2_a(-C_L2E * raw_dwell[w]));
        float dt  = 0.01f + 0.19f * sig;
        #pragma unroll
        for (int o = 16; o; o >>= 1) dt += __shfl_xor_sync(0xFFFFFFFFu, dt, o);
        if ((tid & 31) == 0) sAt[tid >> 5] = dt;
    }
    __syncthreads();

    // chunk = warp (q = tid>>5): all lanes share the waypoint sequence => every
    // sA/sB read is a single-address warp broadcast. pl = lane = point in block.
    const int pl = tid & 31;
    const int q  = tid >> 5;
    const int ip = blockIdx.x * PPB + pl;

    const float px = points[ip * 3 + 0];
    const float py = points[ip * 3 + 1];
    // pz == 0 by construction (reference appends a zero z column)

    // Collapsed scan (validated, rel_err ~2e-7 stable since R4):
    //   orient = bdir(wp127); active_time = sum(dwell);
    //   peak^2 = max_j bxy_j^2 * K^(2(127-j))  -- weight folded into m3, so plain max.
    // Scaled field g = (m3.r)*r - m3*r^2/3 = f*r^5 ; h = g/r^4 ; bxy^2 = |h_xy|^2/r^2.
    float pk0 = 0.0f, pk1 = 0.0f;

    const int j0 = q * CLEN;
    #pragma unroll
    for (int jj = 0; jj < CLEN; jj += 2) {
        {
            const float4 A = sA[j0 + jj];
            const float2 B = sB[j0 + jj];
            float rx = px - A.x, ry = py - A.y;
            float r2  = fmaf(rx, rx, fmaf(ry, ry, A.z));
            float qi  = rcp_a(r2);
            float md3 = fmaf(rx, A.w, fmaf(ry, B.x, B.y));
            float r23 = r2 * C_THIRD;
            float gx  = fmaf(rx, md3, -(A.w * r23));
            float gy  = fmaf(ry, md3, -(B.x * r23));
            float q2  = qi * qi;
            float hx  = gx * q2, hy = gy * q2;
            float v   = fmaf(hx, hx, hy * hy) * qi;
            pk0 = fmaxf(pk0, v);
        }
        {
            const float4 A = sA[j0 + jj + 1];
            const float2 B = sB[j0 + jj + 1];
            float rx = px - A.x, ry = py - A.y;
            float r2  = fmaf(rx, rx, fmaf(ry, ry, A.z));
            float qi  = rcp_a(r2);
            float md3 = fmaf(rx, A.w, fmaf(ry, B.x, B.y));
            float r23 = r2 * C_THIRD;
            float gx  = fmaf(rx, md3, -(A.w * r23));
            float gy  = fmaf(ry, md3, -(B.x * r23));
            float q2  = qi * qi;
            float hx  = gx * q2, hy = gy * q2;
            float v   = fmaf(hx, hx, hy * hy) * qi;
            pk1 = fmaxf(pk1, v);
        }
    }
    float pk = fmaxf(pk0, pk1);

    if (q < 7) sPk[q][pl] = pk;
    __syncthreads();

    // ---- combine 8 chunks (plain max: weights already folded) + orientation ----
    if (q == 7) {
        #pragma unroll
        for (int c = 0; c < 7; c++) pk = fmaxf(pk, sPk[c][pl]);
        float at = (sAt[0] + sAt[1]) + (sAt[2] + sAt[3]);

        // orientation = normalize(g) at waypoint 127 (w=1; positive scale g || field)
        const float4 A = sA[NWP - 1];
        const float2 B = sB[NWP - 1];
        const float2 W = sW127;                 // (cz, m3z)
        float rx = px - A.x, ry = py - A.y;     // rz = -cz
        float r2  = fmaf(rx, rx, fmaf(ry, ry, A.z));
        float md3 = fmaf(rx, A.w, fmaf(ry, B.x, B.y));
        float r23 = r2 * C_THIRD;
        float gx  = fmaf(rx, md3, -(A.w * r23));
        float gy  = fmaf(ry, md3, -(B.x * r23));
        float gz  = fmaf(-W.x, md3, -(W.y * r23));
        float inv = rsqrt_a(fmaf(gx, gx, fmaf(gy, gy, gz * gz)));
        sOut[pl * 5 + 0] = gx * inv;
        sOut[pl * 5 + 1] = gy * inv;
        sOut[pl * 5 + 2] = gz * inv;
        sOut[pl * 5 + 3] = at;
        sOut[pl * 5 + 4] = sqrtf(pk);
    }
    __syncthreads();

    // coalesced output: 160 contiguous floats per block
    if (tid < PPB * 5)
        out[blockIdx.x * (PPB * 5) + tid] = sOut[tid];
}

extern "C" void kernel_launch(void* const* d_in, const int* in_sizes, int n_in,
                              void* d_out, int out_size)
{
    const float* points     = (const float*)d_in[0];
    const float* centers    = (const float*)d_in[1];
    const float* raw_moment = (const float*)d_in[2];
    const float* raw_dwell  = (const float*)d_in[3];
    float* out = (float*)d_out;

    fused_kernel<<<NPTS / PPB, TPB>>>(points, centers, raw_moment, raw_dwell, out);
}

// round 11
// speedup vs baseline: 1.1830x; 1.1830x over previous
#include <cuda_runtime.h>
#include <math.h>

#define NPTS 65536
#define NWP  128
#define TPB  256
#define PPB  64            // 2 points per lane; 8 chunk-warps of 16 waypoints
#define CLEN 16

#define C_L2E 1.4426950408889634f

__device__ __forceinline__ float rsqrt_a(float x){ float r; asm("rsqrt.approx.f32 %0,%1;":"=f"(r):"f"(x)); return r; }
__device__ __forceinline__ float rcp_a  (float x){ float r; asm("rcp.approx.f32 %0,%1;"  :"=f"(r):"f"(x)); return r; }
__device__ __forceinline__ float ex2_a  (float x){ float r; asm("ex2.approx.f32 %0,%1;"  :"=f"(r):"f"(x)); return r; }

__global__ void __launch_bounds__(TPB)
fused_kernel(const float* __restrict__ points,      // [N,3] (z column is exactly 0)
             const float* __restrict__ centers,     // [128,3]
             const float* __restrict__ raw_moment,  // [128,3]
             const float* __restrict__ raw_dwell,   // [128]
             float* __restrict__ out)                // [N,5]
{
    // Per waypoint j, decay weight w = exp(-0.1*(127-j)) folded into moments:
    //   sU = (cx, cy, cz^2, -cz*w*m3z)   [md3 z-term; m3 = 3*moment]
    //   sV = (w*m3x, w*m3y, w*mx, w*my)  [g = (m3.r)*r - m*r^2, exactly f*r^5]
    __shared__ float4 sU[NWP];
    __shared__ float4 sV[NWP];
    __shared__ float2 sW;            // (cz, mz) at waypoint 127 for orientation
    __shared__ float2 sPk[7][32];
    __shared__ float  sAt[4];
    __shared__ float  sOut[PPB * 5];

    const int tid = threadIdx.x;

    // ---- preload: transform waypoints (fast ex2/rcp), reduce sum(dwell) ----
    if (tid < NWP) {
        const int w = tid;
        float cx = centers[w * 3 + 0];
        float cy = centers[w * 3 + 1];
        float cz = centers[w * 3 + 2];
        // tanh(x) = 1 - 2/(e^{2x}+1)
        float tx = 1.0f - 2.0f * rcp_a(ex2_a(2.0f * C_L2E * raw_moment[w * 3 + 0]) + 1.0f);
        float ty = 1.0f - 2.0f * rcp_a(ex2_a(2.0f * C_L2E * raw_moment[w * 3 + 1]) + 1.0f);
        float tz = 1.0f - 2.0f * rcp_a(ex2_a(2.0f * C_L2E * raw_moment[w * 3 + 2]) + 1.0f);
        float wgt = ex2_a((float)(w - 127) * (0.1f * C_L2E));  // exp(-0.1*(127-j))
        float sm1 = 0.05f * wgt;                                // weighted |m| scale
        float sm3 = 3.0f * sm1;
        sU[w] = make_float4(cx, cy, cz * cz, -cz * (sm3 * tz));
        sV[w] = make_float4(sm3 * tx, sm3 * ty, sm1 * tx, sm1 * ty);
        if (w == NWP - 1) sW = make_float2(cz, 0.05f * tz);
        float sig = rcp_a(1.0f + ex2_a(-C_L2E * raw_dwell[w]));
        float dt  = 0.01f + 0.19f * sig;
        #pragma unroll
        for (int o = 16; o; o >>= 1) dt += __shfl_xor_sync(0xFFFFFFFFu, dt, o);
        if ((tid & 31) == 0) sAt[tid >> 5] = dt;
    }
    __syncthreads();

    // chunk = warp (q = tid>>5): all lanes share the waypoint sequence => every
    // sU/sV read is a single-address warp broadcast, amortized over 2 points.
    const int pl = tid & 31;
    const int q  = tid >> 5;
    const int i0 = blockIdx.x * PPB + pl;    // point 0
    const int i1 = i0 + 32;                  // point 1

    const float px0 = points[i0 * 3 + 0], py0 = points[i0 * 3 + 1];
    const float px1 = points[i1 * 3 + 0], py1 = points[i1 * 3 + 1];
    // pz == 0 by construction

    // Collapsed scan (validated, rel_err ~2.6e-7 stable since R4):
    //   orient = bdir(wp127); active_time = sum(dwell);
    //   peak^2 = max_j (w_j^2 * bxy_j^2), weights folded into m  =>  plain max.
    float pkA = 0.0f, pkB = 0.0f;

    const int j0 = q * CLEN;
    #pragma unroll
    for (int jj = 0; jj < CLEN; jj++) {
        const float4 U = sU[j0 + jj];
        const float4 V = sV[j0 + jj];
        {
            float rx = px0 - U.x, ry = py0 - U.y;
            float r2 = fmaf(rx, rx, fmaf(ry, ry, U.z));
            float qi = rcp_a(r2);
            float md = fmaf(rx, V.x, fmaf(ry, V.y, U.w));
            float gx = fmaf(rx, md, -(V.z * r2));
            float gy = fmaf(ry, md, -(V.w * r2));
            float q2 = qi * qi;
            float hx = gx * q2, hy = gy * q2;
            float v  = fmaf(hx, hx, hy * hy) * qi;
            pkA = fmaxf(pkA, v);
        }
        {
            float rx = px1 - U.x, ry = py1 - U.y;
            float r2 = fmaf(rx, rx, fmaf(ry, ry, U.z));
            float qi = rcp_a(r2);
            float md = fmaf(rx, V.x, fmaf(ry, V.y, U.w));
            float gx = fmaf(rx, md, -(V.z * r2));
            float gy = fmaf(ry, md, -(V.w * r2));
            float q2 = qi * qi;
            float hx = gx * q2, hy = gy * q2;
            float v  = fmaf(hx, hx, hy * hy) * qi;
            pkB = fmaxf(pkB, v);
        }
    }

    if (q < 7) sPk[q][pl] = make_float2(pkA, pkB);
    __syncthreads();

    // ---- combine 8 chunks (plain max) + orientation + staging (q == 7) ----
    if (q == 7) {
        #pragma unroll
        for (int c = 0; c < 7; c++) {
            float2 p = sPk[c][pl];
            pkA = fmaxf(pkA, p.x);
            pkB = fmaxf(pkB, p.y);
        }
        float at = (sAt[0] + sAt[1]) + (sAt[2] + sAt[3]);

        const float4 U = sU[NWP - 1];
        const float4 V = sV[NWP - 1];
        const float2 W = sW;                   // (cz, mz), weight = 1 at wp 127
        #pragma unroll
        for (int s = 0; s < 2; s++) {
            float px = s ? px1 : px0;
            float py = s ? py1 : py0;
            float pk = s ? pkB : pkA;
            float rx = px - U.x, ry = py - U.y;       // rz = -cz
            float r2 = fmaf(rx, rx, fmaf(ry, ry, U.z));
            float md = fmaf(rx, V.x, fmaf(ry, V.y, U.w));
            float gx = fmaf(rx, md, -(V.z * r2));
            float gy = fmaf(ry, md, -(V.w * r2));
            float gz = fmaf(-W.x, md, -(W.y * r2));
            float inv = rsqrt_a(fmaf(gx, gx, fmaf(gy, gy, gz * gz)));
            int o = (pl + s * 32) * 5;
            sOut[o + 0] = gx * inv;
            sOut[o + 1] = gy * inv;
            sOut[o + 2] = gz * inv;
            sOut[o + 3] = at;
            sOut[o + 4] = sqrtf(pk);
        }
    }
    __syncthreads();

    // coalesced output: 320 contiguous floats per block
    #pragma unroll
    for (int idx = tid; idx < PPB * 5; idx += TPB)
        out[blockIdx.x * (PPB * 5) + idx] = sOut[idx];
}

extern "C" void kernel_launch(void* const* d_in, const int* in_sizes, int n_in,
                              void* d_out, int out_size)
{
    const float* points     = (const float*)d_in[0];
    const float* centers    = (const float*)d_in[1];
    const float* raw_moment = (const float*)d_in[2];
    const float* raw_dwell  = (const float*)d_in[3];
    float* out = (float*)d_out;

    fused_kernel<<<NPTS / PPB, TPB>>>(points, centers, raw_moment, raw_dwell, out);
}